// round 15
// baseline (speedup 1.0000x reference)
#include <cuda_runtime.h>
#include <cuda_fp16.h>
#include <math.h>
#include <cstdint>

// Problem constants
#define B_   8
#define S_   512
#define D_   512
#define H_   8
#define HID_ 2048
#define DIM_ 64
#define ROWS_ (B_ * S_)        // 4096
#define QKV_N_ (3 * D_)        // 1536
#define EPS_ 0.001f
#define G7_SPLITK_ 2

// ---------------------------------------------------------------------------
// Scratch (device globals; no allocation allowed)
// ---------------------------------------------------------------------------
__device__ __align__(16) half  g_h[ROWS_ * D_];
__device__ __align__(16) half  g_act[ROWS_ * HID_];
__device__ __align__(16) half  g_qkv[ROWS_ * QKV_N_];
__device__ __align__(16) float g_vres[ROWS_ * D_];
__device__ __align__(16) float g_part[G7_SPLITK_ * ROWS_ * D_];  // 16 MB
__device__ __align__(16) half g_wt0a[HID_ * D_];
__device__ __align__(16) half g_wt0b[QKV_N_ * HID_];
__device__ __align__(16) half g_wt1a[HID_ * D_];
__device__ __align__(16) half g_wt1b[D_ * HID_];

// ---------------------------------------------------------------------------
// helpers
// ---------------------------------------------------------------------------
__device__ __forceinline__ void cp_async16(uint32_t d, const void* s) {
    asm volatile("cp.async.cg.shared.global [%0], [%1], 16;"
                 :: "r"(d), "l"(s) : "memory");
}
__device__ __forceinline__ uint32_t smem_u32(const void* p) {
    uint32_t a;
    asm("{ .reg .u64 t; cvta.to.shared.u64 t, %1; cvt.u32.u64 %0, t; }"
        : "=r"(a) : "l"(p));
    return a;
}
__device__ __forceinline__ uint32_t h2_as_u32(half2 h) {
    union { half2 h; uint32_t u; } cvt;
    cvt.h = h;
    return cvt.u;
}
__device__ __forceinline__ void mma16816(float* c, uint32_t a0, uint32_t a1,
                                         uint32_t a2, uint32_t a3,
                                         uint32_t b0, uint32_t b1) {
    asm volatile(
        "mma.sync.aligned.m16n8k16.row.col.f32.f16.f16.f32 "
        "{%0,%1,%2,%3}, {%4,%5,%6,%7}, {%8,%9}, {%0,%1,%2,%3};"
        : "+f"(c[0]), "+f"(c[1]), "+f"(c[2]), "+f"(c[3])
        : "r"(a0), "r"(a1), "r"(a2), "r"(a3), "r"(b0), "r"(b1));
}
__device__ __forceinline__ void ldsm_x4(uint32_t& r0, uint32_t& r1,
                                        uint32_t& r2, uint32_t& r3,
                                        uint32_t addr) {
    asm volatile("ldmatrix.sync.aligned.m8n8.x4.shared.b16 {%0,%1,%2,%3}, [%4];"
                 : "=r"(r0), "=r"(r1), "=r"(r2), "=r"(r3) : "r"(addr));
}

// ---------------------------------------------------------------------------
// Fused weight transpose + fp32->fp16 for all four weights in ONE launch.
// ---------------------------------------------------------------------------
__global__ void transpose4_kernel(const float* __restrict__ W0a, half* __restrict__ wt0a,
                                  const float* __restrict__ W0b, half* __restrict__ wt0b,
                                  const float* __restrict__ W1a, half* __restrict__ wt1a,
                                  const float* __restrict__ W1b, half* __restrict__ wt1b) {
    __shared__ float t[32][33];
    int id = blockIdx.x;
    const float* src; half* dst; int K, N, nx;
    if (id < 1024)      { src = W0a; dst = wt0a; K = D_;   N = HID_;   nx = HID_ / 32; }
    else if (id < 4096) { id -= 1024; src = W0b; dst = wt0b; K = HID_; N = QKV_N_; nx = QKV_N_ / 32; }
    else if (id < 5120) { id -= 4096; src = W1a; dst = wt1a; K = D_;   N = HID_;   nx = HID_ / 32; }
    else                { id -= 5120; src = W1b; dst = wt1b; K = HID_; N = D_;     nx = D_ / 32; }
    int bn = (id % nx) * 32, bk = (id / nx) * 32;
    int x = bn + threadIdx.x;
#pragma unroll
    for (int i = 0; i < 32; i += 8)
        t[threadIdx.y + i][threadIdx.x] = src[(size_t)(bk + threadIdx.y + i) * N + x];
    __syncthreads();
    int xo = bk + threadIdx.x;
#pragma unroll
    for (int i = 0; i < 32; i += 8)
        dst[(size_t)(bn + threadIdx.y + i) * K + xo] =
            __float2half_rn(t[threadIdx.x][threadIdx.y + i]);
}

// ---------------------------------------------------------------------------
// HMMA fp16 GEMM: C[M,N] = A[M,K+] @ Bt[N,K+]^T (+ bias...)
// 128 threads, 4 warps 2x2, warp tile 64x64 (fragment traffic -33%).
// BM=BN=128, BK=64. XOR-swizzled smem, 3-stage cp.async, 96KB -> 2 CTAs/SM.
// EPI: 0 bias->half; 1 bias+relu->half; 2 bias+res->float; 3 splitk fp32 partial
// ---------------------------------------------------------------------------
#define NSTAGE 3
#define TILE_B 16384
#define STAGE_B (2 * TILE_B)

template <int EPI>
__global__ void __launch_bounds__(128, 2)
mma_gemm(const half* __restrict__ A, const half* __restrict__ Bt,
         const float* __restrict__ bias, const float* __restrict__ res,
         void* __restrict__ Cout, int N, int K, int lda) {
    extern __shared__ char smem[];
    uint32_t sS = smem_u32(smem);

    int tid = threadIdx.x;
    int wid = tid >> 5, lane = tid & 31;
    int wm = wid >> 1, wn = wid & 1;    // 2x2 warp grid
    int g = lane >> 2, tg = lane & 3;
    int m0 = blockIdx.y * 128, n0 = blockIdx.x * 128;

    if (EPI == 3) {
        int z = blockIdx.z;
        A  += (size_t)z * K;
        Bt += (size_t)z * K;
    }

    int lt = lane >> 3, lr = lane & 7;
    int row_a = wm * 64 + (lt & 1) * 8 + lr;
    uint32_t aoff = (uint32_t)row_a * 128;
    uint32_t ax = (uint32_t)(row_a & 7);
    uint32_t ac0 = (uint32_t)(lt >> 1);
    int row_b = wn * 64 + (lt >> 1) * 8 + lr;
    uint32_t boff = TILE_B + (uint32_t)row_b * 128;
    uint32_t bx = (uint32_t)(row_b & 7);
    uint32_t bc0 = (uint32_t)(lt & 1);

    float acc[4][8][4];
#pragma unroll
    for (int i = 0; i < 4; i++)
#pragma unroll
        for (int j = 0; j < 8; j++)
#pragma unroll
            for (int r = 0; r < 4; r++) acc[i][j][r] = 0.0f;

    auto load_tiles = [&](int kt, int stage) {
        uint32_t da = sS + stage * STAGE_B;
        uint32_t db = da + TILE_B;
#pragma unroll
        for (int p = 0; p < 8; p++) {
            int idx = tid + p * 128;
            int r = idx >> 3;
            uint32_t c = (uint32_t)(idx & 7);
            cp_async16(da + r * 128 + ((c ^ (r & 7)) << 4),
                       A + (size_t)(m0 + r) * lda + kt * 64 + c * 8);
        }
#pragma unroll
        for (int p = 0; p < 8; p++) {
            int idx = tid + p * 128;
            int r = idx >> 3;
            uint32_t c = (uint32_t)(idx & 7);
            cp_async16(db + r * 128 + ((c ^ (r & 7)) << 4),
                       Bt + (size_t)(n0 + r) * lda + kt * 64 + c * 8);
        }
        asm volatile("cp.async.commit_group;" ::: "memory");
    };

    const int KT = K / 64;
    load_tiles(0, 0);
    if (KT > 1) load_tiles(1, 1);

    int stage = 0;
    for (int kt = 0; kt < KT; kt++) {
        if (kt < KT - 1) {
            asm volatile("cp.async.wait_group 1;" ::: "memory");
        } else {
            asm volatile("cp.async.wait_group 0;" ::: "memory");
        }
        __syncthreads();
        if (kt + 2 < KT) {
            int ns = stage + 2; if (ns >= NSTAGE) ns -= NSTAGE;
            load_tiles(kt + 2, ns);
        }

        uint32_t abase = sS + stage * STAGE_B + aoff;
        uint32_t bbase = sS + stage * STAGE_B + boff;
#pragma unroll
        for (int ks = 0; ks < 4; ks++) {
            uint32_t axs = ((ac0 + 2 * ks) ^ ax) << 4;
            uint32_t bxs = ((bc0 + 2 * ks) ^ bx) << 4;
            uint32_t breg[8][2];
#pragma unroll
            for (int j = 0; j < 4; j++)
                ldsm_x4(breg[2 * j][0], breg[2 * j][1],
                        breg[2 * j + 1][0], breg[2 * j + 1][1],
                        bbase + j * (16 * 128) + bxs);
#pragma unroll
            for (int ma = 0; ma < 4; ma++) {
                uint32_t a0, a1, a2, a3;
                ldsm_x4(a0, a1, a2, a3, abase + ma * (16 * 128) + axs);
#pragma unroll
                for (int na = 0; na < 8; na++)
                    mma16816(acc[ma][na], a0, a1, a2, a3, breg[na][0], breg[na][1]);
            }
        }
        if (++stage >= NSTAGE) stage = 0;
    }

    float* Pf = (EPI == 3)
        ? (float*)Cout + (size_t)blockIdx.z * ROWS_ * N
        : (float*)Cout;

#pragma unroll
    for (int na = 0; na < 8; na++) {
        int col = n0 + wn * 64 + na * 8 + 2 * tg;
        float2 bb = (EPI == 3) ? make_float2(0.f, 0.f)
                               : *(const float2*)(bias + col);
#pragma unroll
        for (int ma = 0; ma < 4; ma++) {
            int row = m0 + wm * 64 + ma * 16 + g;
            float x0 = acc[ma][na][0] + bb.x;
            float x1 = acc[ma][na][1] + bb.y;
            float x2 = acc[ma][na][2] + bb.x;
            float x3 = acc[ma][na][3] + bb.y;
            if (EPI == 1) {
                x0 = fmaxf(x0, 0.0f); x1 = fmaxf(x1, 0.0f);
                x2 = fmaxf(x2, 0.0f); x3 = fmaxf(x3, 0.0f);
            }
            if (EPI == 0 || EPI == 1) {
                half* C = (half*)Cout;
                *(half2*)(C + (size_t)row * N + col)       = __floats2half2_rn(x0, x1);
                *(half2*)(C + (size_t)(row + 8) * N + col) = __floats2half2_rn(x2, x3);
            } else if (EPI == 2) {
                float* C = (float*)Cout;
                float2 r0 = *(const float2*)(res + (size_t)row * N + col);
                float2 r1 = *(const float2*)(res + (size_t)(row + 8) * N + col);
                float2 v0 = {x0 + r0.x, x1 + r0.y};
                float2 v1 = {x2 + r1.x, x3 + r1.y};
                *(float2*)(C + (size_t)row * N + col) = v0;
                *(float2*)(C + (size_t)(row + 8) * N + col) = v1;
            } else {
                float2 v0 = {x0, x1}, v1 = {x2, x3};
                *(float2*)(Pf + (size_t)row * N + col) = v0;
                *(float2*)(Pf + (size_t)(row + 8) * N + col) = v1;
            }
        }
    }
}

// ---------------------------------------------------------------------------
// G7 split-K reduce: out = vres + bias + p0 + p1
// ---------------------------------------------------------------------------
__global__ void reduce_out_kernel(const float* __restrict__ part,
                                  const float* __restrict__ vres,
                                  const float* __restrict__ bias,
                                  float* __restrict__ out) {
    size_t i = (size_t)blockIdx.x * 256 + threadIdx.x;
    size_t e = i * 4;
    int col = (int)(e & (D_ - 1));
    float4 bb = *(const float4*)(bias + col);
    float4 r  = *(const float4*)(vres + e);
    float4 p0 = *(const float4*)(part + e);
    float4 p1 = *(const float4*)(part + (size_t)ROWS_ * D_ + e);
    float4 s = {r.x + bb.x + p0.x + p1.x, r.y + bb.y + p0.y + p1.y,
                r.z + bb.z + p0.z + p1.z, r.w + bb.w + p0.w + p1.w};
    *(float4*)(out + e) = s;
}

// ---------------------------------------------------------------------------
// LayerNorm: one block per row, 128 threads, D=512; outputs HALF
// ---------------------------------------------------------------------------
__global__ void ln_kernel(const float* __restrict__ x,
                          const float* __restrict__ g,
                          const float* __restrict__ b,
                          half* __restrict__ y) {
    int row = blockIdx.x;
    int t   = threadIdx.x;
    const float4* xr = (const float4*)(x + (size_t)row * D_);
    float4 v = xr[t];
    float s  = v.x + v.y + v.z + v.w;
    float ss = v.x * v.x + v.y * v.y + v.z * v.z + v.w * v.w;
#pragma unroll
    for (int o = 16; o; o >>= 1) {
        s  += __shfl_xor_sync(0xffffffffu, s,  o);
        ss += __shfl_xor_sync(0xffffffffu, ss, o);
    }
    __shared__ float sm[4], sm2[4];
    int w = t >> 5;
    if ((t & 31) == 0) { sm[w] = s; sm2[w] = ss; }
    __syncthreads();
    float tot = sm[0] + sm[1] + sm[2] + sm[3];
    float tot2 = sm2[0] + sm2[1] + sm2[2] + sm2[3];
    float mean = tot * (1.0f / D_);
    float var  = tot2 * (1.0f / D_) - mean * mean;
    float rstd = rsqrtf(var + EPS_);

    int c = t * 4;
    float4 gv = *(const float4*)(g + c);
    float4 bv = *(const float4*)(b + c);
    half* yr = y + (size_t)row * D_ + c;
    *(half2*)(yr)     = __floats2half2_rn((v.x - mean) * rstd * gv.x + bv.x,
                                          (v.y - mean) * rstd * gv.y + bv.y);
    *(half2*)(yr + 2) = __floats2half2_rn((v.z - mean) * rstd * gv.z + bv.z,
                                          (v.w - mean) * rstd * gv.w + bv.w);
}

// ---------------------------------------------------------------------------
// HMMA flash attention, 128 q-rows per block (256 thr, 8 warps),
// register prefetch of next K/V tile.
// ---------------------------------------------------------------------------
#define ALD 72
#define VLD 72

__global__ void __launch_bounds__(256)
attn_mma_kernel(const half* __restrict__ qkv, const float* __restrict__ values,
                const float* __restrict__ Wp, const float* __restrict__ bp,
                float* __restrict__ vres) {
    __shared__ half Qs[128][ALD];
    __shared__ half Ks[64][ALD];
    __shared__ half Vs[64][VLD];
    __shared__ half Vt[64][ALD];
    __shared__ float bq[128][2];

    int qt = (int)gridDim.x - 1 - (int)blockIdx.x;
    int h = blockIdx.y, b = blockIdx.z;
    int tid = threadIdx.x;
    int w = tid >> 5, lane = tid & 31;
    int g = lane >> 2, tg = lane & 3;

#pragma unroll
    for (int it = 0; it < 4; it++) {
        int job = tid + it * 256;
        int r = job >> 3, c = job & 7;
        *(uint4*)&Qs[r][c * 8] = *(const uint4*)(
            qkv + (size_t)(b * S_ + qt * 128 + r) * QKV_N_ + h * 192 + c * 8);
    }
    __syncthreads();

    {
        int row = tid >> 1, m = tid & 1;
        float s = 0.0f;
        const float* wrow = Wp + m * D_ + h * DIM_;
        const float* brow = bp + h * DIM_;
#pragma unroll 8
        for (int d = 0; d < 64; d++)
            s += __half2float(Qs[row][d]) * (wrow[d] + brow[d]);
        bq[row][m] = s;
    }

    uint32_t aq[4][4];
#pragma unroll
    for (int ks = 0; ks < 4; ks++) {
        const half* ap = &Qs[16 * w + g][16 * ks + 2 * tg];
        aq[ks][0] = *(const uint32_t*)ap;
        aq[ks][1] = *(const uint32_t*)(ap + 8 * ALD);
        aq[ks][2] = *(const uint32_t*)(ap + 8);
        aq[ks][3] = *(const uint32_t*)(ap + 8 * ALD + 8);
    }

    float m_i[2] = {-1e30f, -1e30f};
    float l_i[2] = {0.0f, 0.0f};
    float O[8][4];
#pragma unroll
    for (int nd = 0; nd < 8; nd++)
#pragma unroll
        for (int r = 0; r < 4; r++) O[nd][r] = 0.0f;

    int qg0 = qt * 128 + 16 * w + g;
    int qg1 = qg0 + 8;
    int nkt = 2 * qt + 2;

    uint4 kreg[2], vreg[2];
    auto gload = [&](int kt) {
#pragma unroll
        for (int it = 0; it < 2; it++) {
            int job = tid + it * 256;
            int r = job >> 3, c = job & 7;
            const half* base = qkv + (size_t)(b * S_ + kt * 64 + r) * QKV_N_ + h * 192;
            kreg[it] = *(const uint4*)(base + 64 + c * 8);
            vreg[it] = *(const uint4*)(base + 128 + c * 8);
        }
    };
    gload(0);

    for (int kt = 0; kt < nkt; kt++) {
        __syncthreads();
#pragma unroll
        for (int it = 0; it < 2; it++) {
            int job = tid + it * 256;
            int r = job >> 3, c = job & 7;
            *(uint4*)&Ks[r][c * 8] = kreg[it];
            *(uint4*)&Vs[r][c * 8] = vreg[it];
        }
        __syncthreads();
        if (kt + 1 < nkt) gload(kt + 1);

#pragma unroll
        for (int it = 0; it < 8; it++) {
            int job = tid + it * 256;
            int r = job & 63, c2 = job >> 6;
            half2 v = *(const half2*)&Vs[r][c2 * 2];
            Vt[c2 * 2 + 0][r] = __low2half(v);
            Vt[c2 * 2 + 1][r] = __high2half(v);
        }

        float sc[8][4];
#pragma unroll
        for (int nb = 0; nb < 8; nb++) {
#pragma unroll
            for (int r = 0; r < 4; r++) sc[nb][r] = 0.0f;
#pragma unroll
            for (int ks = 0; ks < 4; ks++) {
                const half* kp = &Ks[nb * 8 + g][16 * ks + 2 * tg];
                uint32_t b0 = *(const uint32_t*)kp;
                uint32_t b1 = *(const uint32_t*)(kp + 8);
                mma16816(sc[nb], aq[ks][0], aq[ks][1], aq[ks][2], aq[ks][3], b0, b1);
            }
        }
        __syncthreads();

        float b00 = bq[16 * w + g][0],     b01 = bq[16 * w + g][1];
        float b10 = bq[16 * w + g + 8][0], b11 = bq[16 * w + g + 8][1];
        float rm0 = -1e30f, rm1 = -1e30f;
#pragma unroll
        for (int nb = 0; nb < 8; nb++) {
            int kg0 = kt * 64 + nb * 8 + 2 * tg;
            int kg1 = kg0 + 1;
            float v0 = sc[nb][0] * 0.125f + (kg0 == qg0 ? b01 : b00);
            float v1 = sc[nb][1] * 0.125f + (kg1 == qg0 ? b01 : b00);
            float v2 = sc[nb][2] * 0.125f + (kg0 == qg1 ? b11 : b10);
            float v3 = sc[nb][3] * 0.125f + (kg1 == qg1 ? b11 : b10);
            if (kg0 > qg0) v0 = -1e9f;
            if (kg1 > qg0) v1 = -1e9f;
            if (kg0 > qg1) v2 = -1e9f;
            if (kg1 > qg1) v3 = -1e9f;
            sc[nb][0] = v0; sc[nb][1] = v1; sc[nb][2] = v2; sc[nb][3] = v3;
            rm0 = fmaxf(rm0, fmaxf(v0, v1));
            rm1 = fmaxf(rm1, fmaxf(v2, v3));
        }
#pragma unroll
        for (int o = 1; o < 4; o <<= 1) {
            rm0 = fmaxf(rm0, __shfl_xor_sync(0xffffffffu, rm0, o));
            rm1 = fmaxf(rm1, __shfl_xor_sync(0xffffffffu, rm1, o));
        }
        float mn0 = fmaxf(m_i[0], rm0), mn1 = fmaxf(m_i[1], rm1);
        float sc0 = __expf(m_i[0] - mn0), sc1 = __expf(m_i[1] - mn1);
        float ls0 = 0.0f, ls1 = 0.0f;
#pragma unroll
        for (int nb = 0; nb < 8; nb++) {
            sc[nb][0] = __expf(sc[nb][0] - mn0);
            sc[nb][1] = __expf(sc[nb][1] - mn0);
            sc[nb][2] = __expf(sc[nb][2] - mn1);
            sc[nb][3] = __expf(sc[nb][3] - mn1);
            ls0 += sc[nb][0] + sc[nb][1];
            ls1 += sc[nb][2] + sc[nb][3];
        }
#pragma unroll
        for (int o = 1; o < 4; o <<= 1) {
            ls0 += __shfl_xor_sync(0xffffffffu, ls0, o);
            ls1 += __shfl_xor_sync(0xffffffffu, ls1, o);
        }
        l_i[0] = l_i[0] * sc0 + ls0;
        l_i[1] = l_i[1] * sc1 + ls1;
        m_i[0] = mn0; m_i[1] = mn1;
#pragma unroll
        for (int nd = 0; nd < 8; nd++) {
            O[nd][0] *= sc0; O[nd][1] *= sc0;
            O[nd][2] *= sc1; O[nd][3] *= sc1;
        }

        uint32_t pa[4][4];
#pragma unroll
        for (int ks = 0; ks < 4; ks++) {
            pa[ks][0] = h2_as_u32(__floats2half2_rn(sc[2 * ks][0],     sc[2 * ks][1]));
            pa[ks][1] = h2_as_u32(__floats2half2_rn(sc[2 * ks][2],     sc[2 * ks][3]));
            pa[ks][2] = h2_as_u32(__floats2half2_rn(sc[2 * ks + 1][0], sc[2 * ks + 1][1]));
            pa[ks][3] = h2_as_u32(__floats2half2_rn(sc[2 * ks + 1][2], sc[2 * ks + 1][3]));
        }

#pragma unroll
        for (int nd = 0; nd < 8; nd++) {
#pragma unroll
            for (int ks = 0; ks < 4; ks++) {
                const half* vp = &Vt[nd * 8 + g][16 * ks + 2 * tg];
                uint32_t b0 = *(const uint32_t*)vp;
                uint32_t b1 = *(const uint32_t*)(vp + 8);
                mma16816(O[nd], pa[ks][0], pa[ks][1], pa[ks][2], pa[ks][3], b0, b1);
            }
        }
    }

    float inv0 = 1.0f / l_i[0], inv1 = 1.0f / l_i[1];
    size_t row0 = (size_t)(b * S_ + qt * 128 + 16 * w + g);
    size_t row1 = row0 + 8;
#pragma unroll
    for (int nd = 0; nd < 8; nd++) {
        int col = h * DIM_ + nd * 8 + 2 * tg;
        float2 v0 = *(const float2*)(values + row0 * D_ + col);
        float2 v1 = *(const float2*)(values + row1 * D_ + col);
        float2 o0 = {v0.x + O[nd][0] * inv0, v0.y + O[nd][1] * inv0};
        float2 o1 = {v1.x + O[nd][2] * inv1, v1.y + O[nd][3] * inv1};
        *(float2*)(vres + row0 * D_ + col) = o0;
        *(float2*)(vres + row1 * D_ + col) = o1;
    }
}

// ---------------------------------------------------------------------------
// Launcher
// ---------------------------------------------------------------------------
extern "C" void kernel_launch(void* const* d_in, const int* in_sizes, int n_in,
                              void* d_out, int out_size) {
    (void)in_sizes; (void)n_in; (void)out_size;
    const float* values = (const float*)d_in[0];
    const float* ln0_g  = (const float*)d_in[2];
    const float* ln0_b  = (const float*)d_in[3];
    const float* W0a    = (const float*)d_in[4];
    const float* b0a    = (const float*)d_in[5];
    const float* W0b    = (const float*)d_in[6];
    const float* b0b    = (const float*)d_in[7];
    const float* Wp     = (const float*)d_in[8];
    const float* bp     = (const float*)d_in[9];
    const float* ln1_g  = (const float*)d_in[10];
    const float* ln1_b  = (const float*)d_in[11];
    const float* W1a    = (const float*)d_in[12];
    const float* b1a    = (const float*)d_in[13];
    const float* W1b    = (const float*)d_in[14];
    const float* b1b    = (const float*)d_in[15];
    float* out = (float*)d_out;

    half *ph, *pact, *pqkv, *pwt0a, *pwt0b, *pwt1a, *pwt1b;
    float *pvres, *ppart;
    cudaGetSymbolAddress((void**)&ph,    g_h);
    cudaGetSymbolAddress((void**)&pact,  g_act);
    cudaGetSymbolAddress((void**)&pqkv,  g_qkv);
    cudaGetSymbolAddress((void**)&pvres, g_vres);
    cudaGetSymbolAddress((void**)&ppart, g_part);
    cudaGetSymbolAddress((void**)&pwt0a, g_wt0a);
    cudaGetSymbolAddress((void**)&pwt0b, g_wt0b);
    cudaGetSymbolAddress((void**)&pwt1a, g_wt1a);
    cudaGetSymbolAddress((void**)&pwt1b, g_wt1b);

    const int gemm_smem = NSTAGE * STAGE_B;  // 98304 -> 2 CTAs/SM
    cudaFuncSetAttribute(mma_gemm<0>, cudaFuncAttributeMaxDynamicSharedMemorySize, gemm_smem);
    cudaFuncSetAttribute(mma_gemm<1>, cudaFuncAttributeMaxDynamicSharedMemorySize, gemm_smem);
    cudaFuncSetAttribute(mma_gemm<3>, cudaFuncAttributeMaxDynamicSharedMemorySize, gemm_smem);

    // 0) transpose all weights to [N,K] half (single launch)
    transpose4_kernel<<<6144, dim3(32, 8)>>>(W0a, pwt0a, W0b, pwt0b,
                                             W1a, pwt1a, W1b, pwt1b);

    // 1) LN0 -> half
    ln_kernel<<<ROWS_, 128>>>(values, ln0_g, ln0_b, ph);
    // 2) act = relu(h @ W0a + b0a) -> half   (512 CTAs)
    mma_gemm<1><<<dim3(HID_ / 128, ROWS_ / 128), 128, gemm_smem>>>(
        ph, pwt0a, b0a, nullptr, pact, HID_, D_, D_);
    // 3) qkv = act @ W0b + b0b -> half       (384 CTAs)
    mma_gemm<0><<<dim3(QKV_N_ / 128, ROWS_ / 128), 128, gemm_smem>>>(
        pact, pwt0b, b0b, nullptr, pqkv, QKV_N_, HID_, HID_);
    // 4) attention + residual -> vres (fp32)
    attn_mma_kernel<<<dim3(S_ / 128, H_, B_), 256>>>(
        pqkv, values, Wp, bp, pvres);
    // 5) LN1 -> half
    ln_kernel<<<ROWS_, 128>>>(pvres, ln1_g, ln1_b, ph);
    // 6) act = relu(h @ W1a + b1a) -> half   (512 CTAs)
    mma_gemm<1><<<dim3(HID_ / 128, ROWS_ / 128), 128, gemm_smem>>>(
        ph, pwt1a, b1a, nullptr, pact, HID_, D_, D_);
    // 7a) G7 split-K=2 partials (256 CTAs, KT=16, full 128x128 tiles)
    mma_gemm<3><<<dim3(D_ / 128, ROWS_ / 128, G7_SPLITK_), 128, gemm_smem>>>(
        pact, pwt1b, nullptr, nullptr, ppart, D_, HID_ / G7_SPLITK_, HID_);
    // 7b) out = vres + b1b + p0 + p1
    reduce_out_kernel<<<(ROWS_ * D_ / 4) / 256, 256>>>(ppart, pvres, b1b, out);
}

// round 16
// speedup vs baseline: 1.0122x; 1.0122x over previous
#include <cuda_runtime.h>
#include <cuda_fp16.h>
#include <math.h>
#include <cstdint>

// Problem constants
#define B_   8
#define S_   512
#define D_   512
#define H_   8
#define HID_ 2048
#define DIM_ 64
#define ROWS_ (B_ * S_)        // 4096
#define QKV_N_ (3 * D_)        // 1536
#define EPS_ 0.001f
#define G7_SPLITK_ 2

// ---------------------------------------------------------------------------
// Scratch (device globals; no allocation allowed)
// ---------------------------------------------------------------------------
__device__ __align__(16) half  g_h[ROWS_ * D_];
__device__ __align__(16) half  g_act[ROWS_ * HID_];
__device__ __align__(16) half  g_qkv[ROWS_ * QKV_N_];
__device__ __align__(16) float g_vres[ROWS_ * D_];
__device__ __align__(16) float g_part[G7_SPLITK_ * ROWS_ * D_];  // 16 MB
__device__ __align__(16) half g_wt0a[HID_ * D_];
__device__ __align__(16) half g_wt0b[QKV_N_ * HID_];
__device__ __align__(16) half g_wt1a[HID_ * D_];
__device__ __align__(16) half g_wt1b[D_ * HID_];

// ---------------------------------------------------------------------------
// helpers
// ---------------------------------------------------------------------------
__device__ __forceinline__ void cp_async16(uint32_t d, const void* s) {
    asm volatile("cp.async.cg.shared.global [%0], [%1], 16;"
                 :: "r"(d), "l"(s) : "memory");
}
__device__ __forceinline__ uint32_t smem_u32(const void* p) {
    uint32_t a;
    asm("{ .reg .u64 t; cvta.to.shared.u64 t, %1; cvt.u32.u64 %0, t; }"
        : "=r"(a) : "l"(p));
    return a;
}
__device__ __forceinline__ uint32_t h2_as_u32(half2 h) {
    union { half2 h; uint32_t u; } cvt;
    cvt.h = h;
    return cvt.u;
}
__device__ __forceinline__ void mma16816(float* c, uint32_t a0, uint32_t a1,
                                         uint32_t a2, uint32_t a3,
                                         uint32_t b0, uint32_t b1) {
    asm volatile(
        "mma.sync.aligned.m16n8k16.row.col.f32.f16.f16.f32 "
        "{%0,%1,%2,%3}, {%4,%5,%6,%7}, {%8,%9}, {%0,%1,%2,%3};"
        : "+f"(c[0]), "+f"(c[1]), "+f"(c[2]), "+f"(c[3])
        : "r"(a0), "r"(a1), "r"(a2), "r"(a3), "r"(b0), "r"(b1));
}
__device__ __forceinline__ void ldsm_x4(uint32_t& r0, uint32_t& r1,
                                        uint32_t& r2, uint32_t& r3,
                                        uint32_t addr) {
    asm volatile("ldmatrix.sync.aligned.m8n8.x4.shared.b16 {%0,%1,%2,%3}, [%4];"
                 : "=r"(r0), "=r"(r1), "=r"(r2), "=r"(r3) : "r"(addr));
}
__device__ __forceinline__ void ldsm_x2_trans(uint32_t& r0, uint32_t& r1,
                                              uint32_t addr) {
    asm volatile("ldmatrix.sync.aligned.m8n8.x2.trans.shared.b16 {%0,%1}, [%2];"
                 : "=r"(r0), "=r"(r1) : "r"(addr));
}

// ---------------------------------------------------------------------------
// Fused weight transpose + fp32->fp16 for all four weights in ONE launch.
// ---------------------------------------------------------------------------
__global__ void transpose4_kernel(const float* __restrict__ W0a, half* __restrict__ wt0a,
                                  const float* __restrict__ W0b, half* __restrict__ wt0b,
                                  const float* __restrict__ W1a, half* __restrict__ wt1a,
                                  const float* __restrict__ W1b, half* __restrict__ wt1b) {
    __shared__ float t[32][33];
    int id = blockIdx.x;
    const float* src; half* dst; int K, N, nx;
    if (id < 1024)      { src = W0a; dst = wt0a; K = D_;   N = HID_;   nx = HID_ / 32; }
    else if (id < 4096) { id -= 1024; src = W0b; dst = wt0b; K = HID_; N = QKV_N_; nx = QKV_N_ / 32; }
    else if (id < 5120) { id -= 4096; src = W1a; dst = wt1a; K = D_;   N = HID_;   nx = HID_ / 32; }
    else                { id -= 5120; src = W1b; dst = wt1b; K = HID_; N = D_;     nx = D_ / 32; }
    int bn = (id % nx) * 32, bk = (id / nx) * 32;
    int x = bn + threadIdx.x;
#pragma unroll
    for (int i = 0; i < 32; i += 8)
        t[threadIdx.y + i][threadIdx.x] = src[(size_t)(bk + threadIdx.y + i) * N + x];
    __syncthreads();
    int xo = bk + threadIdx.x;
#pragma unroll
    for (int i = 0; i < 32; i += 8)
        dst[(size_t)(bn + threadIdx.y + i) * K + xo] =
            __float2half_rn(t[threadIdx.x][threadIdx.y + i]);
}

// ---------------------------------------------------------------------------
// HMMA fp16 GEMM (R14 config): 256 threads, 8 warps 2x4, warp tile 64x32.
// BM=BN=128, BK=64. XOR-swizzled smem, 3-stage cp.async, 96KB -> 2 CTAs/SM.
// EPI: 0 bias->half; 1 bias+relu->half; 2 bias+res->float; 3 splitk fp32 partial
// ---------------------------------------------------------------------------
#define NSTAGE 3
#define TILE_B 16384
#define STAGE_B (2 * TILE_B)

template <int EPI>
__global__ void __launch_bounds__(256, 2)
mma_gemm(const half* __restrict__ A, const half* __restrict__ Bt,
         const float* __restrict__ bias, const float* __restrict__ res,
         void* __restrict__ Cout, int N, int K, int lda) {
    extern __shared__ char smem[];
    uint32_t sS = smem_u32(smem);

    int tid = threadIdx.x;
    int wid = tid >> 5, lane = tid & 31;
    int wm = wid >> 2, wn = wid & 3;
    int g = lane >> 2, tg = lane & 3;
    int m0 = blockIdx.y * 128, n0 = blockIdx.x * 128;

    if (EPI == 3) {
        int z = blockIdx.z;
        A  += (size_t)z * K;
        Bt += (size_t)z * K;
    }

    int lt = lane >> 3, lr = lane & 7;
    int row_a = wm * 64 + (lt & 1) * 8 + lr;
    uint32_t aoff = (uint32_t)row_a * 128;
    uint32_t ax = (uint32_t)(row_a & 7);
    uint32_t ac0 = (uint32_t)(lt >> 1);
    int row_b = wn * 32 + (lt >> 1) * 8 + lr;
    uint32_t boff = TILE_B + (uint32_t)row_b * 128;
    uint32_t bx = (uint32_t)(row_b & 7);
    uint32_t bc0 = (uint32_t)(lt & 1);

    float acc[4][4][4];
#pragma unroll
    for (int i = 0; i < 4; i++)
#pragma unroll
        for (int j = 0; j < 4; j++)
#pragma unroll
            for (int r = 0; r < 4; r++) acc[i][j][r] = 0.0f;

    auto load_tiles = [&](int kt, int stage) {
        uint32_t da = sS + stage * STAGE_B;
        uint32_t db = da + TILE_B;
#pragma unroll
        for (int p = 0; p < 4; p++) {
            int idx = tid + p * 256;
            int r = idx >> 3;
            uint32_t c = (uint32_t)(idx & 7);
            cp_async16(da + r * 128 + ((c ^ (r & 7)) << 4),
                       A + (size_t)(m0 + r) * lda + kt * 64 + c * 8);
        }
#pragma unroll
        for (int p = 0; p < 4; p++) {
            int idx = tid + p * 256;
            int r = idx >> 3;
            uint32_t c = (uint32_t)(idx & 7);
            cp_async16(db + r * 128 + ((c ^ (r & 7)) << 4),
                       Bt + (size_t)(n0 + r) * lda + kt * 64 + c * 8);
        }
        asm volatile("cp.async.commit_group;" ::: "memory");
    };

    const int KT = K / 64;
    load_tiles(0, 0);
    if (KT > 1) load_tiles(1, 1);

    int stage = 0;
    for (int kt = 0; kt < KT; kt++) {
        if (kt < KT - 1) {
            asm volatile("cp.async.wait_group 1;" ::: "memory");
        } else {
            asm volatile("cp.async.wait_group 0;" ::: "memory");
        }
        __syncthreads();
        if (kt + 2 < KT) {
            int ns = stage + 2; if (ns >= NSTAGE) ns -= NSTAGE;
            load_tiles(kt + 2, ns);
        }

        uint32_t abase = sS + stage * STAGE_B + aoff;
        uint32_t bbase = sS + stage * STAGE_B + boff;
#pragma unroll
        for (int ks = 0; ks < 4; ks++) {
            uint32_t axs = ((ac0 + 2 * ks) ^ ax) << 4;
            uint32_t bxs = ((bc0 + 2 * ks) ^ bx) << 4;
            uint32_t breg[4][2];
#pragma unroll
            for (int j = 0; j < 2; j++)
                ldsm_x4(breg[2 * j][0], breg[2 * j][1],
                        breg[2 * j + 1][0], breg[2 * j + 1][1],
                        bbase + j * (16 * 128) + bxs);
#pragma unroll
            for (int ma = 0; ma < 4; ma++) {
                uint32_t a0, a1, a2, a3;
                ldsm_x4(a0, a1, a2, a3, abase + ma * (16 * 128) + axs);
#pragma unroll
                for (int na = 0; na < 4; na++)
                    mma16816(acc[ma][na], a0, a1, a2, a3, breg[na][0], breg[na][1]);
            }
        }
        if (++stage >= NSTAGE) stage = 0;
    }

    float* Pf = (EPI == 3)
        ? (float*)Cout + (size_t)blockIdx.z * ROWS_ * N
        : (float*)Cout;

#pragma unroll
    for (int na = 0; na < 4; na++) {
        int col = n0 + wn * 32 + na * 8 + 2 * tg;
        float2 bb = (EPI == 3) ? make_float2(0.f, 0.f)
                               : *(const float2*)(bias + col);
#pragma unroll
        for (int ma = 0; ma < 4; ma++) {
            int row = m0 + wm * 64 + ma * 16 + g;
            float x0 = acc[ma][na][0] + bb.x;
            float x1 = acc[ma][na][1] + bb.y;
            float x2 = acc[ma][na][2] + bb.x;
            float x3 = acc[ma][na][3] + bb.y;
            if (EPI == 1) {
                x0 = fmaxf(x0, 0.0f); x1 = fmaxf(x1, 0.0f);
                x2 = fmaxf(x2, 0.0f); x3 = fmaxf(x3, 0.0f);
            }
            if (EPI == 0 || EPI == 1) {
                half* C = (half*)Cout;
                *(half2*)(C + (size_t)row * N + col)       = __floats2half2_rn(x0, x1);
                *(half2*)(C + (size_t)(row + 8) * N + col) = __floats2half2_rn(x2, x3);
            } else if (EPI == 2) {
                float* C = (float*)Cout;
                float2 r0 = *(const float2*)(res + (size_t)row * N + col);
                float2 r1 = *(const float2*)(res + (size_t)(row + 8) * N + col);
                float2 v0 = {x0 + r0.x, x1 + r0.y};
                float2 v1 = {x2 + r1.x, x3 + r1.y};
                *(float2*)(C + (size_t)row * N + col) = v0;
                *(float2*)(C + (size_t)(row + 8) * N + col) = v1;
            } else {
                float2 v0 = {x0, x1}, v1 = {x2, x3};
                *(float2*)(Pf + (size_t)row * N + col) = v0;
                *(float2*)(Pf + (size_t)(row + 8) * N + col) = v1;
            }
        }
    }
}

// ---------------------------------------------------------------------------
// G7 split-K reduce: out = vres + bias + p0 + p1
// ---------------------------------------------------------------------------
__global__ void reduce_out_kernel(const float* __restrict__ part,
                                  const float* __restrict__ vres,
                                  const float* __restrict__ bias,
                                  float* __restrict__ out) {
    size_t i = (size_t)blockIdx.x * 256 + threadIdx.x;
    size_t e = i * 4;
    int col = (int)(e & (D_ - 1));
    float4 bb = *(const float4*)(bias + col);
    float4 r  = *(const float4*)(vres + e);
    float4 p0 = *(const float4*)(part + e);
    float4 p1 = *(const float4*)(part + (size_t)ROWS_ * D_ + e);
    float4 s = {r.x + bb.x + p0.x + p1.x, r.y + bb.y + p0.y + p1.y,
                r.z + bb.z + p0.z + p1.z, r.w + bb.w + p0.w + p1.w};
    *(float4*)(out + e) = s;
}

// ---------------------------------------------------------------------------
// LayerNorm: one block per row, 128 threads, D=512; outputs HALF
// ---------------------------------------------------------------------------
__global__ void ln_kernel(const float* __restrict__ x,
                          const float* __restrict__ g,
                          const float* __restrict__ b,
                          half* __restrict__ y) {
    int row = blockIdx.x;
    int t   = threadIdx.x;
    const float4* xr = (const float4*)(x + (size_t)row * D_);
    float4 v = xr[t];
    float s  = v.x + v.y + v.z + v.w;
    float ss = v.x * v.x + v.y * v.y + v.z * v.z + v.w * v.w;
#pragma unroll
    for (int o = 16; o; o >>= 1) {
        s  += __shfl_xor_sync(0xffffffffu, s,  o);
        ss += __shfl_xor_sync(0xffffffffu, ss, o);
    }
    __shared__ float sm[4], sm2[4];
    int w = t >> 5;
    if ((t & 31) == 0) { sm[w] = s; sm2[w] = ss; }
    __syncthreads();
    float tot = sm[0] + sm[1] + sm[2] + sm[3];
    float tot2 = sm2[0] + sm2[1] + sm2[2] + sm2[3];
    float mean = tot * (1.0f / D_);
    float var  = tot2 * (1.0f / D_) - mean * mean;
    float rstd = rsqrtf(var + EPS_);

    int c = t * 4;
    float4 gv = *(const float4*)(g + c);
    float4 bv = *(const float4*)(b + c);
    half* yr = y + (size_t)row * D_ + c;
    *(half2*)(yr)     = __floats2half2_rn((v.x - mean) * rstd * gv.x + bv.x,
                                          (v.y - mean) * rstd * gv.y + bv.y);
    *(half2*)(yr + 2) = __floats2half2_rn((v.z - mean) * rstd * gv.z + bv.z,
                                          (v.w - mean) * rstd * gv.w + bv.w);
}

// ---------------------------------------------------------------------------
// HMMA flash attention, 128 q-rows per block (256 thr, 8 warps).
// Double-buffered K/V smem + register prefetch -> ONE barrier per k-tile.
// PV B-fragments via ldmatrix.x2.trans directly from k-major Vs (no Vt).
// ---------------------------------------------------------------------------
#define ALD 72

__global__ void __launch_bounds__(256)
attn_mma_kernel(const half* __restrict__ qkv, const float* __restrict__ values,
                const float* __restrict__ Wp, const float* __restrict__ bp,
                float* __restrict__ vres) {
    __shared__ half Qs[128][ALD];
    __shared__ half Ks[2][64][ALD];
    __shared__ half Vs[2][64][ALD];
    __shared__ float bq[128][2];

    int qt = (int)gridDim.x - 1 - (int)blockIdx.x;  // heavy first
    int h = blockIdx.y, b = blockIdx.z;
    int tid = threadIdx.x;
    int w = tid >> 5, lane = tid & 31;
    int g = lane >> 2, tg = lane & 3;
    int l16 = lane & 15;

    // load Q tile
#pragma unroll
    for (int it = 0; it < 4; it++) {
        int job = tid + it * 256;
        int r = job >> 3, c = job & 7;
        *(uint4*)&Qs[r][c * 8] = *(const uint4*)(
            qkv + (size_t)(b * S_ + qt * 128 + r) * QKV_N_ + h * 192 + c * 8);
    }
    __syncthreads();

    // per-row bias scalars
    {
        int row = tid >> 1, m = tid & 1;
        float s = 0.0f;
        const float* wrow = Wp + m * D_ + h * DIM_;
        const float* brow = bp + h * DIM_;
#pragma unroll 8
        for (int d = 0; d < 64; d++)
            s += __half2float(Qs[row][d]) * (wrow[d] + brow[d]);
        bq[row][m] = s;
    }

    // Q a-frags
    uint32_t aq[4][4];
#pragma unroll
    for (int ks = 0; ks < 4; ks++) {
        const half* ap = &Qs[16 * w + g][16 * ks + 2 * tg];
        aq[ks][0] = *(const uint32_t*)ap;
        aq[ks][1] = *(const uint32_t*)(ap + 8 * ALD);
        aq[ks][2] = *(const uint32_t*)(ap + 8);
        aq[ks][3] = *(const uint32_t*)(ap + 8 * ALD + 8);
    }

    float m_i[2] = {-1e30f, -1e30f};
    float l_i[2] = {0.0f, 0.0f};
    float O[8][4];
#pragma unroll
    for (int nd = 0; nd < 8; nd++)
#pragma unroll
        for (int r = 0; r < 4; r++) O[nd][r] = 0.0f;

    int qg0 = qt * 128 + 16 * w + g;
    int qg1 = qg0 + 8;
    int nkt = 2 * qt + 2;

    uint4 kreg[2], vreg[2];
    auto gload = [&](int kt) {
#pragma unroll
        for (int it = 0; it < 2; it++) {
            int job = tid + it * 256;
            int r = job >> 3, c = job & 7;
            const half* base = qkv + (size_t)(b * S_ + kt * 64 + r) * QKV_N_ + h * 192;
            kreg[it] = *(const uint4*)(base + 64 + c * 8);
            vreg[it] = *(const uint4*)(base + 128 + c * 8);
        }
    };
    auto sstore = [&](int buf) {
#pragma unroll
        for (int it = 0; it < 2; it++) {
            int job = tid + it * 256;
            int r = job >> 3, c = job & 7;
            *(uint4*)&Ks[buf][r][c * 8] = kreg[it];
            *(uint4*)&Vs[buf][r][c * 8] = vreg[it];
        }
    };

    // prologue: tile 0 into buf0; tile 1 into regs
    gload(0);
    sstore(0);
    if (nkt > 1) gload(1);
    __syncthreads();  // buf0 published; bq published

    for (int kt = 0; kt < nkt; kt++) {
        int buf = kt & 1;
        // publish tile kt+1 into buf^1 (regs hold it); prefetch kt+2
        if (kt + 1 < nkt) sstore(buf ^ 1);
        if (kt + 2 < nkt) gload(kt + 2);

        // S = Q K^T from Ks[buf]
        float sc[8][4];
#pragma unroll
        for (int nb = 0; nb < 8; nb++) {
#pragma unroll
            for (int r = 0; r < 4; r++) sc[nb][r] = 0.0f;
#pragma unroll
            for (int ks = 0; ks < 4; ks++) {
                const half* kp = &Ks[buf][nb * 8 + g][16 * ks + 2 * tg];
                uint32_t b0 = *(const uint32_t*)kp;
                uint32_t b1 = *(const uint32_t*)(kp + 8);
                mma16816(sc[nb], aq[ks][0], aq[ks][1], aq[ks][2], aq[ks][3], b0, b1);
            }
        }

        // bias + causal mask + online softmax
        float b00 = bq[16 * w + g][0],     b01 = bq[16 * w + g][1];
        float b10 = bq[16 * w + g + 8][0], b11 = bq[16 * w + g + 8][1];
        float rm0 = -1e30f, rm1 = -1e30f;
#pragma unroll
        for (int nb = 0; nb < 8; nb++) {
            int kg0 = kt * 64 + nb * 8 + 2 * tg;
            int kg1 = kg0 + 1;
            float v0 = sc[nb][0] * 0.125f + (kg0 == qg0 ? b01 : b00);
            float v1 = sc[nb][1] * 0.125f + (kg1 == qg0 ? b01 : b00);
            float v2 = sc[nb][2] * 0.125f + (kg0 == qg1 ? b11 : b10);
            float v3 = sc[nb][3] * 0.125f + (kg1 == qg1 ? b11 : b10);
            if (kg0 > qg0) v0 = -1e9f;
            if (kg1 > qg0) v1 = -1e9f;
            if (kg0 > qg1) v2 = -1e9f;
            if (kg1 > qg1) v3 = -1e9f;
            sc[nb][0] = v0; sc[nb][1] = v1; sc[nb][2] = v2; sc[nb][3] = v3;
            rm0 = fmaxf(rm0, fmaxf(v0, v1));
            rm1 = fmaxf(rm1, fmaxf(v2, v3));
        }
#pragma unroll
        for (int o = 1; o < 4; o <<= 1) {
            rm0 = fmaxf(rm0, __shfl_xor_sync(0xffffffffu, rm0, o));
            rm1 = fmaxf(rm1, __shfl_xor_sync(0xffffffffu, rm1, o));
        }
        float mn0 = fmaxf(m_i[0], rm0), mn1 = fmaxf(m_i[1], rm1);
        float sc0 = __expf(m_i[0] - mn0), sc1 = __expf(m_i[1] - mn1);
        float ls0 = 0.0f, ls1 = 0.0f;
#pragma unroll
        for (int nb = 0; nb < 8; nb++) {
            sc[nb][0] = __expf(sc[nb][0] - mn0);
            sc[nb][1] = __expf(sc[nb][1] - mn0);
            sc[nb][2] = __expf(sc[nb][2] - mn1);
            sc[nb][3] = __expf(sc[nb][3] - mn1);
            ls0 += sc[nb][0] + sc[nb][1];
            ls1 += sc[nb][2] + sc[nb][3];
        }
#pragma unroll
        for (int o = 1; o < 4; o <<= 1) {
            ls0 += __shfl_xor_sync(0xffffffffu, ls0, o);
            ls1 += __shfl_xor_sync(0xffffffffu, ls1, o);
        }
        l_i[0] = l_i[0] * sc0 + ls0;
        l_i[1] = l_i[1] * sc1 + ls1;
        m_i[0] = mn0; m_i[1] = mn1;
#pragma unroll
        for (int nd = 0; nd < 8; nd++) {
            O[nd][0] *= sc0; O[nd][1] *= sc0;
            O[nd][2] *= sc1; O[nd][3] *= sc1;
        }

        // pack P into A-frags
        uint32_t pa[4][4];
#pragma unroll
        for (int ks = 0; ks < 4; ks++) {
            pa[ks][0] = h2_as_u32(__floats2half2_rn(sc[2 * ks][0],     sc[2 * ks][1]));
            pa[ks][1] = h2_as_u32(__floats2half2_rn(sc[2 * ks][2],     sc[2 * ks][3]));
            pa[ks][2] = h2_as_u32(__floats2half2_rn(sc[2 * ks + 1][0], sc[2 * ks + 1][1]));
            pa[ks][3] = h2_as_u32(__floats2half2_rn(sc[2 * ks + 1][2], sc[2 * ks + 1][3]));
        }

        // O += P V; B-frags via ldmatrix.trans from k-major Vs[buf]
        // for (nd, ks): tile rows = Vs[16*ks + l16][nd*8 .. nd*8+7]
#pragma unroll
        for (int nd = 0; nd < 8; nd++) {
#pragma unroll
            for (int ks = 0; ks < 4; ks++) {
                uint32_t addr = smem_u32(&Vs[buf][16 * ks + l16][nd * 8]);
                uint32_t b0, b1;
                ldsm_x2_trans(b0, b1, addr);
                mma16816(O[nd], pa[ks][0], pa[ks][1], pa[ks][2], pa[ks][3], b0, b1);
            }
        }

        __syncthreads();  // buf^1 published for next iter; reads of buf done
    }

    // epilogue: vres = values + O / l
    float inv0 = 1.0f / l_i[0], inv1 = 1.0f / l_i[1];
    size_t row0 = (size_t)(b * S_ + qt * 128 + 16 * w + g);
    size_t row1 = row0 + 8;
#pragma unroll
    for (int nd = 0; nd < 8; nd++) {
        int col = h * DIM_ + nd * 8 + 2 * tg;
        float2 v0 = *(const float2*)(values + row0 * D_ + col);
        float2 v1 = *(const float2*)(values + row1 * D_ + col);
        float2 o0 = {v0.x + O[nd][0] * inv0, v0.y + O[nd][1] * inv0};
        float2 o1 = {v1.x + O[nd][2] * inv1, v1.y + O[nd][3] * inv1};
        *(float2*)(vres + row0 * D_ + col) = o0;
        *(float2*)(vres + row1 * D_ + col) = o1;
    }
}

// ---------------------------------------------------------------------------
// Launcher
// ---------------------------------------------------------------------------
extern "C" void kernel_launch(void* const* d_in, const int* in_sizes, int n_in,
                              void* d_out, int out_size) {
    (void)in_sizes; (void)n_in; (void)out_size;
    const float* values = (const float*)d_in[0];
    const float* ln0_g  = (const float*)d_in[2];
    const float* ln0_b  = (const float*)d_in[3];
    const float* W0a    = (const float*)d_in[4];
    const float* b0a    = (const float*)d_in[5];
    const float* W0b    = (const float*)d_in[6];
    const float* b0b    = (const float*)d_in[7];
    const float* Wp     = (const float*)d_in[8];
    const float* bp     = (const float*)d_in[9];
    const float* ln1_g  = (const float*)d_in[10];
    const float* ln1_b  = (const float*)d_in[11];
    const float* W1a    = (const float*)d_in[12];
    const float* b1a    = (const float*)d_in[13];
    const float* W1b    = (const float*)d_in[14];
    const float* b1b    = (const float*)d_in[15];
    float* out = (float*)d_out;

    half *ph, *pact, *pqkv, *pwt0a, *pwt0b, *pwt1a, *pwt1b;
    float *pvres, *ppart;
    cudaGetSymbolAddress((void**)&ph,    g_h);
    cudaGetSymbolAddress((void**)&pact,  g_act);
    cudaGetSymbolAddress((void**)&pqkv,  g_qkv);
    cudaGetSymbolAddress((void**)&pvres, g_vres);
    cudaGetSymbolAddress((void**)&ppart, g_part);
    cudaGetSymbolAddress((void**)&pwt0a, g_wt0a);
    cudaGetSymbolAddress((void**)&pwt0b, g_wt0b);
    cudaGetSymbolAddress((void**)&pwt1a, g_wt1a);
    cudaGetSymbolAddress((void**)&pwt1b, g_wt1b);

    const int gemm_smem = NSTAGE * STAGE_B;  // 98304 -> 2 CTAs/SM
    cudaFuncSetAttribute(mma_gemm<0>, cudaFuncAttributeMaxDynamicSharedMemorySize, gemm_smem);
    cudaFuncSetAttribute(mma_gemm<1>, cudaFuncAttributeMaxDynamicSharedMemorySize, gemm_smem);
    cudaFuncSetAttribute(mma_gemm<3>, cudaFuncAttributeMaxDynamicSharedMemorySize, gemm_smem);

    // 0) transpose all weights to [N,K] half (single launch)
    transpose4_kernel<<<6144, dim3(32, 8)>>>(W0a, pwt0a, W0b, pwt0b,
                                             W1a, pwt1a, W1b, pwt1b);

    // 1) LN0 -> half
    ln_kernel<<<ROWS_, 128>>>(values, ln0_g, ln0_b, ph);
    // 2) act = relu(h @ W0a + b0a) -> half
    mma_gemm<1><<<dim3(HID_ / 128, ROWS_ / 128), 256, gemm_smem>>>(
        ph, pwt0a, b0a, nullptr, pact, HID_, D_, D_);
    // 3) qkv = act @ W0b + b0b -> half
    mma_gemm<0><<<dim3(QKV_N_ / 128, ROWS_ / 128), 256, gemm_smem>>>(
        pact, pwt0b, b0b, nullptr, pqkv, QKV_N_, HID_, HID_);
    // 4) attention + residual -> vres (fp32)
    attn_mma_kernel<<<dim3(S_ / 128, H_, B_), 256>>>(
        pqkv, values, Wp, bp, pvres);
    // 5) LN1 -> half
    ln_kernel<<<ROWS_, 128>>>(pvres, ln1_g, ln1_b, ph);
    // 6) act = relu(h @ W1a + b1a) -> half
    mma_gemm<1><<<dim3(HID_ / 128, ROWS_ / 128), 256, gemm_smem>>>(
        ph, pwt1a, b1a, nullptr, pact, HID_, D_, D_);
    // 7a) G7 split-K=2 partials
    mma_gemm<3><<<dim3(D_ / 128, ROWS_ / 128, G7_SPLITK_), 256, gemm_smem>>>(
        pact, pwt1b, nullptr, nullptr, ppart, D_, HID_ / G7_SPLITK_, HID_);
    // 7b) out = vres + b1b + p0 + p1
    reduce_out_kernel<<<(ROWS_ * D_ / 4) / 256, 256>>>(ppart, pvres, b1b, out);
}

// round 17
// speedup vs baseline: 1.0223x; 1.0100x over previous
#include <cuda_runtime.h>
#include <cuda_fp16.h>
#include <math.h>
#include <cstdint>

// Problem constants
#define B_   8
#define S_   512
#define D_   512
#define H_   8
#define HID_ 2048
#define DIM_ 64
#define ROWS_ (B_ * S_)        // 4096
#define QKV_N_ (3 * D_)        // 1536
#define EPS_ 0.001f
#define G7_SPLITK_ 2

// ---------------------------------------------------------------------------
// Scratch (device globals; no allocation allowed)
// ---------------------------------------------------------------------------
__device__ __align__(16) half  g_h[ROWS_ * D_];
__device__ __align__(16) half  g_act[ROWS_ * HID_];
__device__ __align__(16) half  g_qkv[ROWS_ * QKV_N_];
__device__ __align__(16) float g_vres[ROWS_ * D_];
__device__ __align__(16) float g_part[G7_SPLITK_ * ROWS_ * D_];  // 16 MB
__device__ __align__(16) half g_wt0a[HID_ * D_];
__device__ __align__(16) half g_wt0b[QKV_N_ * HID_];
__device__ __align__(16) half g_wt1a[HID_ * D_];
__device__ __align__(16) half g_wt1b[D_ * HID_];

// ---------------------------------------------------------------------------
// helpers
// ---------------------------------------------------------------------------
__device__ __forceinline__ void cp_async16(uint32_t d, const void* s) {
    asm volatile("cp.async.cg.shared.global [%0], [%1], 16;"
                 :: "r"(d), "l"(s) : "memory");
}
__device__ __forceinline__ uint32_t smem_u32(const void* p) {
    uint32_t a;
    asm("{ .reg .u64 t; cvta.to.shared.u64 t, %1; cvt.u32.u64 %0, t; }"
        : "=r"(a) : "l"(p));
    return a;
}
__device__ __forceinline__ uint32_t h2_as_u32(half2 h) {
    union { half2 h; uint32_t u; } cvt;
    cvt.h = h;
    return cvt.u;
}
__device__ __forceinline__ void mma16816(float* c, uint32_t a0, uint32_t a1,
                                         uint32_t a2, uint32_t a3,
                                         uint32_t b0, uint32_t b1) {
    asm volatile(
        "mma.sync.aligned.m16n8k16.row.col.f32.f16.f16.f32 "
        "{%0,%1,%2,%3}, {%4,%5,%6,%7}, {%8,%9}, {%0,%1,%2,%3};"
        : "+f"(c[0]), "+f"(c[1]), "+f"(c[2]), "+f"(c[3])
        : "r"(a0), "r"(a1), "r"(a2), "r"(a3), "r"(b0), "r"(b1));
}
__device__ __forceinline__ void ldsm_x4(uint32_t& r0, uint32_t& r1,
                                        uint32_t& r2, uint32_t& r3,
                                        uint32_t addr) {
    asm volatile("ldmatrix.sync.aligned.m8n8.x4.shared.b16 {%0,%1,%2,%3}, [%4];"
                 : "=r"(r0), "=r"(r1), "=r"(r2), "=r"(r3) : "r"(addr));
}
__device__ __forceinline__ void ldsm_x2_trans(uint32_t& r0, uint32_t& r1,
                                              uint32_t addr) {
    asm volatile("ldmatrix.sync.aligned.m8n8.x2.trans.shared.b16 {%0,%1}, [%2];"
                 : "=r"(r0), "=r"(r1) : "r"(addr));
}

// ---------------------------------------------------------------------------
// FUSED startup: weight transposes (blocks 0..6143) + LN0 (blocks 6144..8191).
// 256 threads per block for both paths.
// ---------------------------------------------------------------------------
__global__ void startup_kernel(const float* __restrict__ W0a, half* __restrict__ wt0a,
                               const float* __restrict__ W0b, half* __restrict__ wt0b,
                               const float* __restrict__ W1a, half* __restrict__ wt1a,
                               const float* __restrict__ W1b, half* __restrict__ wt1b,
                               const float* __restrict__ values,
                               const float* __restrict__ ln0_g,
                               const float* __restrict__ ln0_b,
                               half* __restrict__ h_out) {
    int bid = blockIdx.x;
    if (bid < 6144) {
        // ---- transpose path (32x32 tile, 32x8 thread layout from 256 flat)
        __shared__ float t[32][33];
        int tx = threadIdx.x & 31, ty = threadIdx.x >> 5;  // 32x8
        const float* src; half* dst; int K, N, nx;
        int id = bid;
        if (id < 1024)      { src = W0a; dst = wt0a; K = D_;   N = HID_;   nx = HID_ / 32; }
        else if (id < 4096) { id -= 1024; src = W0b; dst = wt0b; K = HID_; N = QKV_N_; nx = QKV_N_ / 32; }
        else if (id < 5120) { id -= 4096; src = W1a; dst = wt1a; K = D_;   N = HID_;   nx = HID_ / 32; }
        else                { id -= 5120; src = W1b; dst = wt1b; K = HID_; N = D_;     nx = D_ / 32; }
        int bn = (id % nx) * 32, bk = (id / nx) * 32;
        int x = bn + tx;
#pragma unroll
        for (int i = 0; i < 32; i += 8)
            t[ty + i][tx] = src[(size_t)(bk + ty + i) * N + x];
        __syncthreads();
        int xo = bk + tx;
#pragma unroll
        for (int i = 0; i < 32; i += 8)
            dst[(size_t)(bn + ty + i) * K + xo] = __float2half_rn(t[tx][ty + i]);
    } else {
        // ---- LN0 path: 2 rows per block (128 threads each)
        int sub = threadIdx.x >> 7;         // 0/1: which row
        int t   = threadIdx.x & 127;
        int row = (bid - 6144) * 2 + sub;
        const float4* xr = (const float4*)(values + (size_t)row * D_);
        float4 v = xr[t];
        float s  = v.x + v.y + v.z + v.w;
        float ss = v.x * v.x + v.y * v.y + v.z * v.z + v.w * v.w;
#pragma unroll
        for (int o = 16; o; o >>= 1) {
            s  += __shfl_xor_sync(0xffffffffu, s,  o);
            ss += __shfl_xor_sync(0xffffffffu, ss, o);
        }
        __shared__ float sm[2][4], sm2[2][4];
        int w = t >> 5;
        if ((t & 31) == 0) { sm[sub][w] = s; sm2[sub][w] = ss; }
        __syncthreads();
        float tot  = sm[sub][0] + sm[sub][1] + sm[sub][2] + sm[sub][3];
        float tot2 = sm2[sub][0] + sm2[sub][1] + sm2[sub][2] + sm2[sub][3];
        float mean = tot * (1.0f / D_);
        float var  = tot2 * (1.0f / D_) - mean * mean;
        float rstd = rsqrtf(var + EPS_);
        int c = t * 4;
        float4 gv = *(const float4*)(ln0_g + c);
        float4 bv = *(const float4*)(ln0_b + c);
        half* yr = h_out + (size_t)row * D_ + c;
        *(half2*)(yr)     = __floats2half2_rn((v.x - mean) * rstd * gv.x + bv.x,
                                              (v.y - mean) * rstd * gv.y + bv.y);
        *(half2*)(yr + 2) = __floats2half2_rn((v.z - mean) * rstd * gv.z + bv.z,
                                              (v.w - mean) * rstd * gv.w + bv.w);
    }
}

// ---------------------------------------------------------------------------
// HMMA fp16 GEMM (R14/R16 config): 256 threads, 8 warps 2x4, warp tile 64x32.
// BM=BN=128, BK=64. XOR-swizzled smem, 3-stage cp.async, 96KB -> 2 CTAs/SM.
// EPI: 0 bias->half; 1 bias+relu->half; 2 bias+res->float; 3 splitk fp32 partial
// ---------------------------------------------------------------------------
#define NSTAGE 3
#define TILE_B 16384
#define STAGE_B (2 * TILE_B)

template <int EPI>
__global__ void __launch_bounds__(256, 2)
mma_gemm(const half* __restrict__ A, const half* __restrict__ Bt,
         const float* __restrict__ bias, const float* __restrict__ res,
         void* __restrict__ Cout, int N, int K, int lda) {
    extern __shared__ char smem[];
    uint32_t sS = smem_u32(smem);

    int tid = threadIdx.x;
    int wid = tid >> 5, lane = tid & 31;
    int wm = wid >> 2, wn = wid & 3;
    int g = lane >> 2, tg = lane & 3;
    int m0 = blockIdx.y * 128, n0 = blockIdx.x * 128;

    if (EPI == 3) {
        int z = blockIdx.z;
        A  += (size_t)z * K;
        Bt += (size_t)z * K;
    }

    int lt = lane >> 3, lr = lane & 7;
    int row_a = wm * 64 + (lt & 1) * 8 + lr;
    uint32_t aoff = (uint32_t)row_a * 128;
    uint32_t ax = (uint32_t)(row_a & 7);
    uint32_t ac0 = (uint32_t)(lt >> 1);
    int row_b = wn * 32 + (lt >> 1) * 8 + lr;
    uint32_t boff = TILE_B + (uint32_t)row_b * 128;
    uint32_t bx = (uint32_t)(row_b & 7);
    uint32_t bc0 = (uint32_t)(lt & 1);

    float acc[4][4][4];
#pragma unroll
    for (int i = 0; i < 4; i++)
#pragma unroll
        for (int j = 0; j < 4; j++)
#pragma unroll
            for (int r = 0; r < 4; r++) acc[i][j][r] = 0.0f;

    auto load_tiles = [&](int kt, int stage) {
        uint32_t da = sS + stage * STAGE_B;
        uint32_t db = da + TILE_B;
#pragma unroll
        for (int p = 0; p < 4; p++) {
            int idx = tid + p * 256;
            int r = idx >> 3;
            uint32_t c = (uint32_t)(idx & 7);
            cp_async16(da + r * 128 + ((c ^ (r & 7)) << 4),
                       A + (size_t)(m0 + r) * lda + kt * 64 + c * 8);
        }
#pragma unroll
        for (int p = 0; p < 4; p++) {
            int idx = tid + p * 256;
            int r = idx >> 3;
            uint32_t c = (uint32_t)(idx & 7);
            cp_async16(db + r * 128 + ((c ^ (r & 7)) << 4),
                       Bt + (size_t)(n0 + r) * lda + kt * 64 + c * 8);
        }
        asm volatile("cp.async.commit_group;" ::: "memory");
    };

    const int KT = K / 64;
    load_tiles(0, 0);
    if (KT > 1) load_tiles(1, 1);

    int stage = 0;
    for (int kt = 0; kt < KT; kt++) {
        if (kt < KT - 1) {
            asm volatile("cp.async.wait_group 1;" ::: "memory");
        } else {
            asm volatile("cp.async.wait_group 0;" ::: "memory");
        }
        __syncthreads();
        if (kt + 2 < KT) {
            int ns = stage + 2; if (ns >= NSTAGE) ns -= NSTAGE;
            load_tiles(kt + 2, ns);
        }

        uint32_t abase = sS + stage * STAGE_B + aoff;
        uint32_t bbase = sS + stage * STAGE_B + boff;
#pragma unroll
        for (int ks = 0; ks < 4; ks++) {
            uint32_t axs = ((ac0 + 2 * ks) ^ ax) << 4;
            uint32_t bxs = ((bc0 + 2 * ks) ^ bx) << 4;
            uint32_t breg[4][2];
#pragma unroll
            for (int j = 0; j < 2; j++)
                ldsm_x4(breg[2 * j][0], breg[2 * j][1],
                        breg[2 * j + 1][0], breg[2 * j + 1][1],
                        bbase + j * (16 * 128) + bxs);
#pragma unroll
            for (int ma = 0; ma < 4; ma++) {
                uint32_t a0, a1, a2, a3;
                ldsm_x4(a0, a1, a2, a3, abase + ma * (16 * 128) + axs);
#pragma unroll
                for (int na = 0; na < 4; na++)
                    mma16816(acc[ma][na], a0, a1, a2, a3, breg[na][0], breg[na][1]);
            }
        }
        if (++stage >= NSTAGE) stage = 0;
    }

    float* Pf = (EPI == 3)
        ? (float*)Cout + (size_t)blockIdx.z * ROWS_ * N
        : (float*)Cout;

#pragma unroll
    for (int na = 0; na < 4; na++) {
        int col = n0 + wn * 32 + na * 8 + 2 * tg;
        float2 bb = (EPI == 3) ? make_float2(0.f, 0.f)
                               : *(const float2*)(bias + col);
#pragma unroll
        for (int ma = 0; ma < 4; ma++) {
            int row = m0 + wm * 64 + ma * 16 + g;
            float x0 = acc[ma][na][0] + bb.x;
            float x1 = acc[ma][na][1] + bb.y;
            float x2 = acc[ma][na][2] + bb.x;
            float x3 = acc[ma][na][3] + bb.y;
            if (EPI == 1) {
                x0 = fmaxf(x0, 0.0f); x1 = fmaxf(x1, 0.0f);
                x2 = fmaxf(x2, 0.0f); x3 = fmaxf(x3, 0.0f);
            }
            if (EPI == 0 || EPI == 1) {
                half* C = (half*)Cout;
                *(half2*)(C + (size_t)row * N + col)       = __floats2half2_rn(x0, x1);
                *(half2*)(C + (size_t)(row + 8) * N + col) = __floats2half2_rn(x2, x3);
            } else if (EPI == 2) {
                float* C = (float*)Cout;
                float2 r0 = *(const float2*)(res + (size_t)row * N + col);
                float2 r1 = *(const float2*)(res + (size_t)(row + 8) * N + col);
                float2 v0 = {x0 + r0.x, x1 + r0.y};
                float2 v1 = {x2 + r1.x, x3 + r1.y};
                *(float2*)(C + (size_t)row * N + col) = v0;
                *(float2*)(C + (size_t)(row + 8) * N + col) = v1;
            } else {
                float2 v0 = {x0, x1}, v1 = {x2, x3};
                *(float2*)(Pf + (size_t)row * N + col) = v0;
                *(float2*)(Pf + (size_t)(row + 8) * N + col) = v1;
            }
        }
    }
}

// ---------------------------------------------------------------------------
// G7 split-K reduce: out = vres + bias + p0 + p1
// ---------------------------------------------------------------------------
__global__ void reduce_out_kernel(const float* __restrict__ part,
                                  const float* __restrict__ vres,
                                  const float* __restrict__ bias,
                                  float* __restrict__ out) {
    size_t i = (size_t)blockIdx.x * 256 + threadIdx.x;
    size_t e = i * 4;
    int col = (int)(e & (D_ - 1));
    float4 bb = *(const float4*)(bias + col);
    float4 r  = *(const float4*)(vres + e);
    float4 p0 = *(const float4*)(part + e);
    float4 p1 = *(const float4*)(part + (size_t)ROWS_ * D_ + e);
    float4 s = {r.x + bb.x + p0.x + p1.x, r.y + bb.y + p0.y + p1.y,
                r.z + bb.z + p0.z + p1.z, r.w + bb.w + p0.w + p1.w};
    *(float4*)(out + e) = s;
}

// ---------------------------------------------------------------------------
// LayerNorm (standalone, used for LN1): one block per row, 128 threads.
// ---------------------------------------------------------------------------
__global__ void ln_kernel(const float* __restrict__ x,
                          const float* __restrict__ g,
                          const float* __restrict__ b,
                          half* __restrict__ y) {
    int row = blockIdx.x;
    int t   = threadIdx.x;
    const float4* xr = (const float4*)(x + (size_t)row * D_);
    float4 v = xr[t];
    float s  = v.x + v.y + v.z + v.w;
    float ss = v.x * v.x + v.y * v.y + v.z * v.z + v.w * v.w;
#pragma unroll
    for (int o = 16; o; o >>= 1) {
        s  += __shfl_xor_sync(0xffffffffu, s,  o);
        ss += __shfl_xor_sync(0xffffffffu, ss, o);
    }
    __shared__ float sm[4], sm2[4];
    int w = t >> 5;
    if ((t & 31) == 0) { sm[w] = s; sm2[w] = ss; }
    __syncthreads();
    float tot = sm[0] + sm[1] + sm[2] + sm[3];
    float tot2 = sm2[0] + sm2[1] + sm2[2] + sm2[3];
    float mean = tot * (1.0f / D_);
    float var  = tot2 * (1.0f / D_) - mean * mean;
    float rstd = rsqrtf(var + EPS_);

    int c = t * 4;
    float4 gv = *(const float4*)(g + c);
    float4 bv = *(const float4*)(b + c);
    half* yr = y + (size_t)row * D_ + c;
    *(half2*)(yr)     = __floats2half2_rn((v.x - mean) * rstd * gv.x + bv.x,
                                          (v.y - mean) * rstd * gv.y + bv.y);
    *(half2*)(yr + 2) = __floats2half2_rn((v.z - mean) * rstd * gv.z + bv.z,
                                          (v.w - mean) * rstd * gv.w + bv.w);
}

// ---------------------------------------------------------------------------
// HMMA flash attention (R16 config): 128 q-rows, 256 thr, 8 warps,
// double-buffered K/V smem + register prefetch, ldmatrix.trans PV.
// ---------------------------------------------------------------------------
#define ALD 72

__global__ void __launch_bounds__(256)
attn_mma_kernel(const half* __restrict__ qkv, const float* __restrict__ values,
                const float* __restrict__ Wp, const float* __restrict__ bp,
                float* __restrict__ vres) {
    __shared__ half Qs[128][ALD];
    __shared__ half Ks[2][64][ALD];
    __shared__ half Vs[2][64][ALD];
    __shared__ float bq[128][2];

    int qt = (int)gridDim.x - 1 - (int)blockIdx.x;
    int h = blockIdx.y, b = blockIdx.z;
    int tid = threadIdx.x;
    int w = tid >> 5, lane = tid & 31;
    int g = lane >> 2, tg = lane & 3;
    int l16 = lane & 15;

#pragma unroll
    for (int it = 0; it < 4; it++) {
        int job = tid + it * 256;
        int r = job >> 3, c = job & 7;
        *(uint4*)&Qs[r][c * 8] = *(const uint4*)(
            qkv + (size_t)(b * S_ + qt * 128 + r) * QKV_N_ + h * 192 + c * 8);
    }
    __syncthreads();

    {
        int row = tid >> 1, m = tid & 1;
        float s = 0.0f;
        const float* wrow = Wp + m * D_ + h * DIM_;
        const float* brow = bp + h * DIM_;
#pragma unroll 8
        for (int d = 0; d < 64; d++)
            s += __half2float(Qs[row][d]) * (wrow[d] + brow[d]);
        bq[row][m] = s;
    }

    uint32_t aq[4][4];
#pragma unroll
    for (int ks = 0; ks < 4; ks++) {
        const half* ap = &Qs[16 * w + g][16 * ks + 2 * tg];
        aq[ks][0] = *(const uint32_t*)ap;
        aq[ks][1] = *(const uint32_t*)(ap + 8 * ALD);
        aq[ks][2] = *(const uint32_t*)(ap + 8);
        aq[ks][3] = *(const uint32_t*)(ap + 8 * ALD + 8);
    }

    float m_i[2] = {-1e30f, -1e30f};
    float l_i[2] = {0.0f, 0.0f};
    float O[8][4];
#pragma unroll
    for (int nd = 0; nd < 8; nd++)
#pragma unroll
        for (int r = 0; r < 4; r++) O[nd][r] = 0.0f;

    int qg0 = qt * 128 + 16 * w + g;
    int qg1 = qg0 + 8;
    int nkt = 2 * qt + 2;

    uint4 kreg[2], vreg[2];
    auto gload = [&](int kt) {
#pragma unroll
        for (int it = 0; it < 2; it++) {
            int job = tid + it * 256;
            int r = job >> 3, c = job & 7;
            const half* base = qkv + (size_t)(b * S_ + kt * 64 + r) * QKV_N_ + h * 192;
            kreg[it] = *(const uint4*)(base + 64 + c * 8);
            vreg[it] = *(const uint4*)(base + 128 + c * 8);
        }
    };
    auto sstore = [&](int buf) {
#pragma unroll
        for (int it = 0; it < 2; it++) {
            int job = tid + it * 256;
            int r = job >> 3, c = job & 7;
            *(uint4*)&Ks[buf][r][c * 8] = kreg[it];
            *(uint4*)&Vs[buf][r][c * 8] = vreg[it];
        }
    };

    gload(0);
    sstore(0);
    if (nkt > 1) gload(1);
    __syncthreads();

    for (int kt = 0; kt < nkt; kt++) {
        int buf = kt & 1;
        if (kt + 1 < nkt) sstore(buf ^ 1);
        if (kt + 2 < nkt) gload(kt + 2);

        float sc[8][4];
#pragma unroll
        for (int nb = 0; nb < 8; nb++) {
#pragma unroll
            for (int r = 0; r < 4; r++) sc[nb][r] = 0.0f;
#pragma unroll
            for (int ks = 0; ks < 4; ks++) {
                const half* kp = &Ks[buf][nb * 8 + g][16 * ks + 2 * tg];
                uint32_t b0 = *(const uint32_t*)kp;
                uint32_t b1 = *(const uint32_t*)(kp + 8);
                mma16816(sc[nb], aq[ks][0], aq[ks][1], aq[ks][2], aq[ks][3], b0, b1);
            }
        }

        float b00 = bq[16 * w + g][0],     b01 = bq[16 * w + g][1];
        float b10 = bq[16 * w + g + 8][0], b11 = bq[16 * w + g + 8][1];
        float rm0 = -1e30f, rm1 = -1e30f;
#pragma unroll
        for (int nb = 0; nb < 8; nb++) {
            int kg0 = kt * 64 + nb * 8 + 2 * tg;
            int kg1 = kg0 + 1;
            float v0 = sc[nb][0] * 0.125f + (kg0 == qg0 ? b01 : b00);
            float v1 = sc[nb][1] * 0.125f + (kg1 == qg0 ? b01 : b00);
            float v2 = sc[nb][2] * 0.125f + (kg0 == qg1 ? b11 : b10);
            float v3 = sc[nb][3] * 0.125f + (kg1 == qg1 ? b11 : b10);
            if (kg0 > qg0) v0 = -1e9f;
            if (kg1 > qg0) v1 = -1e9f;
            if (kg0 > qg1) v2 = -1e9f;
            if (kg1 > qg1) v3 = -1e9f;
            sc[nb][0] = v0; sc[nb][1] = v1; sc[nb][2] = v2; sc[nb][3] = v3;
            rm0 = fmaxf(rm0, fmaxf(v0, v1));
            rm1 = fmaxf(rm1, fmaxf(v2, v3));
        }
#pragma unroll
        for (int o = 1; o < 4; o <<= 1) {
            rm0 = fmaxf(rm0, __shfl_xor_sync(0xffffffffu, rm0, o));
            rm1 = fmaxf(rm1, __shfl_xor_sync(0xffffffffu, rm1, o));
        }
        float mn0 = fmaxf(m_i[0], rm0), mn1 = fmaxf(m_i[1], rm1);
        float sc0 = __expf(m_i[0] - mn0), sc1 = __expf(m_i[1] - mn1);
        float ls0 = 0.0f, ls1 = 0.0f;
#pragma unroll
        for (int nb = 0; nb < 8; nb++) {
            sc[nb][0] = __expf(sc[nb][0] - mn0);
            sc[nb][1] = __expf(sc[nb][1] - mn0);
            sc[nb][2] = __expf(sc[nb][2] - mn1);
            sc[nb][3] = __expf(sc[nb][3] - mn1);
            ls0 += sc[nb][0] + sc[nb][1];
            ls1 += sc[nb][2] + sc[nb][3];
        }
#pragma unroll
        for (int o = 1; o < 4; o <<= 1) {
            ls0 += __shfl_xor_sync(0xffffffffu, ls0, o);
            ls1 += __shfl_xor_sync(0xffffffffu, ls1, o);
        }
        l_i[0] = l_i[0] * sc0 + ls0;
        l_i[1] = l_i[1] * sc1 + ls1;
        m_i[0] = mn0; m_i[1] = mn1;
#pragma unroll
        for (int nd = 0; nd < 8; nd++) {
            O[nd][0] *= sc0; O[nd][1] *= sc0;
            O[nd][2] *= sc1; O[nd][3] *= sc1;
        }

        uint32_t pa[4][4];
#pragma unroll
        for (int ks = 0; ks < 4; ks++) {
            pa[ks][0] = h2_as_u32(__floats2half2_rn(sc[2 * ks][0],     sc[2 * ks][1]));
            pa[ks][1] = h2_as_u32(__floats2half2_rn(sc[2 * ks][2],     sc[2 * ks][3]));
            pa[ks][2] = h2_as_u32(__floats2half2_rn(sc[2 * ks + 1][0], sc[2 * ks + 1][1]));
            pa[ks][3] = h2_as_u32(__floats2half2_rn(sc[2 * ks + 1][2], sc[2 * ks + 1][3]));
        }

#pragma unroll
        for (int nd = 0; nd < 8; nd++) {
#pragma unroll
            for (int ks = 0; ks < 4; ks++) {
                uint32_t addr = smem_u32(&Vs[buf][16 * ks + l16][nd * 8]);
                uint32_t b0, b1;
                ldsm_x2_trans(b0, b1, addr);
                mma16816(O[nd], pa[ks][0], pa[ks][1], pa[ks][2], pa[ks][3], b0, b1);
            }
        }

        __syncthreads();
    }

    float inv0 = 1.0f / l_i[0], inv1 = 1.0f / l_i[1];
    size_t row0 = (size_t)(b * S_ + qt * 128 + 16 * w + g);
    size_t row1 = row0 + 8;
#pragma unroll
    for (int nd = 0; nd < 8; nd++) {
        int col = h * DIM_ + nd * 8 + 2 * tg;
        float2 v0 = *(const float2*)(values + row0 * D_ + col);
        float2 v1 = *(const float2*)(values + row1 * D_ + col);
        float2 o0 = {v0.x + O[nd][0] * inv0, v0.y + O[nd][1] * inv0};
        float2 o1 = {v1.x + O[nd][2] * inv1, v1.y + O[nd][3] * inv1};
        *(float2*)(vres + row0 * D_ + col) = o0;
        *(float2*)(vres + row1 * D_ + col) = o1;
    }
}

// ---------------------------------------------------------------------------
// Launcher
// ---------------------------------------------------------------------------
extern "C" void kernel_launch(void* const* d_in, const int* in_sizes, int n_in,
                              void* d_out, int out_size) {
    (void)in_sizes; (void)n_in; (void)out_size;
    const float* values = (const float*)d_in[0];
    const float* ln0_g  = (const float*)d_in[2];
    const float* ln0_b  = (const float*)d_in[3];
    const float* W0a    = (const float*)d_in[4];
    const float* b0a    = (const float*)d_in[5];
    const float* W0b    = (const float*)d_in[6];
    const float* b0b    = (const float*)d_in[7];
    const float* Wp     = (const float*)d_in[8];
    const float* bp     = (const float*)d_in[9];
    const float* ln1_g  = (const float*)d_in[10];
    const float* ln1_b  = (const float*)d_in[11];
    const float* W1a    = (const float*)d_in[12];
    const float* b1a    = (const float*)d_in[13];
    const float* W1b    = (const float*)d_in[14];
    const float* b1b    = (const float*)d_in[15];
    float* out = (float*)d_out;

    half *ph, *pact, *pqkv, *pwt0a, *pwt0b, *pwt1a, *pwt1b;
    float *pvres, *ppart;
    cudaGetSymbolAddress((void**)&ph,    g_h);
    cudaGetSymbolAddress((void**)&pact,  g_act);
    cudaGetSymbolAddress((void**)&pqkv,  g_qkv);
    cudaGetSymbolAddress((void**)&pvres, g_vres);
    cudaGetSymbolAddress((void**)&ppart, g_part);
    cudaGetSymbolAddress((void**)&pwt0a, g_wt0a);
    cudaGetSymbolAddress((void**)&pwt0b, g_wt0b);
    cudaGetSymbolAddress((void**)&pwt1a, g_wt1a);
    cudaGetSymbolAddress((void**)&pwt1b, g_wt1b);

    const int gemm_smem = NSTAGE * STAGE_B;  // 98304 -> 2 CTAs/SM
    cudaFuncSetAttribute(mma_gemm<0>, cudaFuncAttributeMaxDynamicSharedMemorySize, gemm_smem);
    cudaFuncSetAttribute(mma_gemm<1>, cudaFuncAttributeMaxDynamicSharedMemorySize, gemm_smem);
    cudaFuncSetAttribute(mma_gemm<3>, cudaFuncAttributeMaxDynamicSharedMemorySize, gemm_smem);

    // 0) FUSED: weight transposes + LN0 in one launch (independent work)
    startup_kernel<<<6144 + ROWS_ / 2, 256>>>(
        W0a, pwt0a, W0b, pwt0b, W1a, pwt1a, W1b, pwt1b,
        values, ln0_g, ln0_b, ph);

    // 1) act = relu(h @ W0a + b0a) -> half
    mma_gemm<1><<<dim3(HID_ / 128, ROWS_ / 128), 256, gemm_smem>>>(
        ph, pwt0a, b0a, nullptr, pact, HID_, D_, D_);
    // 2) qkv = act @ W0b + b0b -> half
    mma_gemm<0><<<dim3(QKV_N_ / 128, ROWS_ / 128), 256, gemm_smem>>>(
        pact, pwt0b, b0b, nullptr, pqkv, QKV_N_, HID_, HID_);
    // 3) attention + residual -> vres (fp32)
    attn_mma_kernel<<<dim3(S_ / 128, H_, B_), 256>>>(
        pqkv, values, Wp, bp, pvres);
    // 4) LN1 -> half
    ln_kernel<<<ROWS_, 128>>>(pvres, ln1_g, ln1_b, ph);
    // 5) act = relu(h @ W1a + b1a) -> half
    mma_gemm<1><<<dim3(HID_ / 128, ROWS_ / 128), 256, gemm_smem>>>(
        ph, pwt1a, b1a, nullptr, pact, HID_, D_, D_);
    // 6a) G7 split-K=2 partials
    mma_gemm<3><<<dim3(D_ / 128, ROWS_ / 128, G7_SPLITK_), 256, gemm_smem>>>(
        pact, pwt1b, nullptr, nullptr, ppart, D_, HID_ / G7_SPLITK_, HID_);
    // 6b) out = vres + b1b + p0 + p1
    reduce_out_kernel<<<(ROWS_ * D_ / 4) / 256, 256>>>(ppart, pvres, b1b, out);
}